// round 3
// baseline (speedup 1.0000x reference)
#include <cuda_runtime.h>

#define B_DIM 32
#define L_DIM 4096
#define D_DIM 768
#define D4 (D_DIM / 4)   // 192 float4 per position

// Scratch for per-row SEP/EOS positions (no cudaMalloc allowed).
__device__ int g_sep[B_DIM];
__device__ int g_eos[B_DIM];

// Kernel 1: per-row first occurrence of token 4 (SEP) and token 2 (EOS).
// Handles int32 or int64 tokens: for int64 LE data every odd 32-bit word is 0
// (tokens in [2, 32000]); probe 4 odd words to decide.
__global__ void find_markers_kernel(const int* __restrict__ x32) {
    __shared__ int s_sep, s_eos;
    const int b = blockIdx.x;
    if (threadIdx.x == 0) { s_sep = L_DIM; s_eos = L_DIM; }
    __syncthreads();

    const bool is64 = (x32[1] == 0) & (x32[3] == 0) & (x32[5] == 0) & (x32[7] == 0);

    int lsep = L_DIM, leos = L_DIM;
    if (!is64) {
        const int4* row = (const int4*)(x32 + (long long)b * L_DIM);
        for (int k = threadIdx.x; k < L_DIM / 4; k += blockDim.x) {
            const int4 v = row[k];
            const int base = 4 * k;
            if (v.x == 4) lsep = min(lsep, base + 0);
            if (v.y == 4) lsep = min(lsep, base + 1);
            if (v.z == 4) lsep = min(lsep, base + 2);
            if (v.w == 4) lsep = min(lsep, base + 3);
            if (v.x == 2) leos = min(leos, base + 0);
            if (v.y == 2) leos = min(leos, base + 1);
            if (v.z == 2) leos = min(leos, base + 2);
            if (v.w == 2) leos = min(leos, base + 3);
        }
    } else {
        // int64: tokens at even 32-bit words (x, z of each int4)
        const int4* row = (const int4*)(x32 + (long long)b * L_DIM * 2);
        for (int k = threadIdx.x; k < L_DIM / 2; k += blockDim.x) {
            const int4 v = row[k];
            const int base = 2 * k;
            if (v.x == 4) lsep = min(lsep, base + 0);
            if (v.z == 4) lsep = min(lsep, base + 1);
            if (v.x == 2) leos = min(leos, base + 0);
            if (v.z == 2) leos = min(leos, base + 1);
        }
    }
    #pragma unroll
    for (int off = 16; off > 0; off >>= 1) {
        lsep = min(lsep, __shfl_down_sync(0xFFFFFFFFu, lsep, off));
        leos = min(leos, __shfl_down_sync(0xFFFFFFFFu, leos, off));
    }
    if ((threadIdx.x & 31) == 0) {
        atomicMin(&s_sep, lsep);
        atomicMin(&s_eos, leos);
    }
    __syncthreads();
    if (threadIdx.x == 0) {
        g_sep[b] = s_sep;
        g_eos[b] = s_eos;
    }
}

// Kernel 2: warp-per-position, grid-stride. Each warp writes the full 768-float
// row of one position as 6 coalesced 512B streaming stores. No divisions.
__global__ void __launch_bounds__(256) write_embedding_kernel(
    const float4* __restrict__ W4, float4* __restrict__ out) {
    const int lane   = threadIdx.x & 31;
    const int warp0  = (blockIdx.x * blockDim.x + threadIdx.x) >> 5;
    const int nwarps = (gridDim.x * blockDim.x) >> 5;

    for (int p = warp0; p < B_DIM * L_DIM; p += nwarps) {
        const int b = p >> 12;           // / L_DIM
        const int l = p & (L_DIM - 1);   // % L_DIM
        const int seg = (l < g_sep[b]) ? 1 : ((l < g_eos[b]) ? 2 : 0);

        const float4* __restrict__ wrow = W4 + seg * D4 + lane;
        float4* __restrict__ orow = out + (long long)p * D4 + lane;
        #pragma unroll
        for (int j = 0; j < 6; j++) {
            __stcs(orow + 32 * j, __ldg(wrow + 32 * j));
        }
    }
}

extern "C" void kernel_launch(void* const* d_in, const int* in_sizes, int n_in,
                              void* d_out, int out_size) {
    // Identify inputs by element count: x has B*L, W has 3*D.
    const int* x;
    const float* W;
    if (in_sizes[0] == B_DIM * L_DIM) {
        x = (const int*)d_in[0];
        W = (const float*)d_in[1];
    } else {
        x = (const int*)d_in[1];
        W = (const float*)d_in[0];
    }

    find_markers_kernel<<<B_DIM, 256>>>(x);

    // ~8 CTAs per SM on 148 SMs; each warp loops ~14 positions.
    write_embedding_kernel<<<1184, 256>>>((const float4*)W, (float4*)d_out);
}

// round 5
// speedup vs baseline: 1.1546x; 1.1546x over previous
#include <cuda_runtime.h>

#define B_DIM 32
#define L_DIM 4096
#define D_DIM 768
#define D4 (D_DIM / 4)      // 192 float4 per position
#define P_PER_BLK 4

// Scratch for per-row SEP/EOS positions (no cudaMalloc allowed).
__device__ int g_sep[B_DIM];
__device__ int g_eos[B_DIM];

// Kernel 1: per-row first occurrence of token 4 (SEP) and token 2 (EOS).
// Handles int32 or int64 tokens: for int64 LE data every odd 32-bit word is 0
// (tokens in [2, 32000]); probe 4 odd words to decide.
__global__ void find_markers_kernel(const int* __restrict__ x32) {
    __shared__ int s_sep, s_eos;
    const int b = blockIdx.x;
    if (threadIdx.x == 0) { s_sep = L_DIM; s_eos = L_DIM; }
    __syncthreads();

    const bool is64 = (x32[1] == 0) & (x32[3] == 0) & (x32[5] == 0) & (x32[7] == 0);

    int lsep = L_DIM, leos = L_DIM;
    if (!is64) {
        const int4* row = (const int4*)(x32 + (long long)b * L_DIM);
        for (int k = threadIdx.x; k < L_DIM / 4; k += blockDim.x) {
            const int4 v = row[k];
            const int base = 4 * k;
            if (v.x == 4) lsep = min(lsep, base + 0);
            if (v.y == 4) lsep = min(lsep, base + 1);
            if (v.z == 4) lsep = min(lsep, base + 2);
            if (v.w == 4) lsep = min(lsep, base + 3);
            if (v.x == 2) leos = min(leos, base + 0);
            if (v.y == 2) leos = min(leos, base + 1);
            if (v.z == 2) leos = min(leos, base + 2);
            if (v.w == 2) leos = min(leos, base + 3);
        }
    } else {
        const int4* row = (const int4*)(x32 + (long long)b * L_DIM * 2);
        for (int k = threadIdx.x; k < L_DIM / 2; k += blockDim.x) {
            const int4 v = row[k];
            const int base = 2 * k;
            if (v.x == 4) lsep = min(lsep, base + 0);
            if (v.z == 4) lsep = min(lsep, base + 1);
            if (v.x == 2) leos = min(leos, base + 0);
            if (v.z == 2) leos = min(leos, base + 1);
        }
    }
    #pragma unroll
    for (int off = 16; off > 0; off >>= 1) {
        lsep = min(lsep, __shfl_down_sync(0xFFFFFFFFu, lsep, off));
        leos = min(leos, __shfl_down_sync(0xFFFFFFFFu, leos, off));
    }
    if ((threadIdx.x & 31) == 0) {
        atomicMin(&s_sep, lsep);
        atomicMin(&s_eos, leos);
    }
    __syncthreads();
    if (threadIdx.x == 0) {
        g_sep[b] = s_sep;
        g_eos[b] = s_eos;
    }
}

// Kernel 2: block of 192 threads = one full D-row per position; each block
// writes P_PER_BLK consecutive positions -> 4 independent coalesced STG.128
// per thread. No divisions anywhere.
__global__ void __launch_bounds__(192) write_embedding_kernel(
    const float4* __restrict__ W4, float4* __restrict__ out) {
    const int tid = threadIdx.x;
    const int p0  = blockIdx.x * P_PER_BLK;

    // Resolve all segments first so the address math is independent and the
    // compiler can front-batch the loads/stores.
    int seg[P_PER_BLK];
    #pragma unroll
    for (int j = 0; j < P_PER_BLK; j++) {
        const int p = p0 + j;
        const int b = p >> 12;           // / L_DIM
        const int l = p & (L_DIM - 1);   // % L_DIM
        seg[j] = (l < g_sep[b]) ? 1 : ((l < g_eos[b]) ? 2 : 0);
    }

    float4 v[P_PER_BLK];
    #pragma unroll
    for (int j = 0; j < P_PER_BLK; j++)
        v[j] = __ldg(W4 + seg[j] * D4 + tid);

    float4* __restrict__ o = out + (long long)p0 * D4 + tid;
    #pragma unroll
    for (int j = 0; j < P_PER_BLK; j++)
        o[(long long)j * D4] = v[j];
}

extern "C" void kernel_launch(void* const* d_in, const int* in_sizes, int n_in,
                              void* d_out, int out_size) {
    // Identify inputs by element count: x has B*L, W has 3*D.
    const int* x;
    const float* W;
    if (in_sizes[0] == B_DIM * L_DIM) {
        x = (const int*)d_in[0];
        W = (const float*)d_in[1];
    } else {
        x = (const int*)d_in[1];
        W = (const float*)d_in[0];
    }

    find_markers_kernel<<<B_DIM, 256>>>(x);

    // B*L / P_PER_BLK = 131072 / 4 = 32768 blocks
    write_embedding_kernel<<<(B_DIM * L_DIM) / P_PER_BLK, 192>>>(
        (const float4*)W, (float4*)d_out);
}